// round 6
// baseline (speedup 1.0000x reference)
#include <cuda_runtime.h>
#include <math.h>

#define B_   64
#define C_   8
#define N_   112
#define LD   113
#define KS   7
#define HALO 3
#define NMAT (B_*C_)
#define NPIX (N_*N_)
#define NTRI 6328              /* 112*113/2 lower-triangle elements */
#define T_   256
#define EPT  25                /* elements per thread (256*25 = 6400 >= 6328) */
#define WPC  (C_*KS*KS)        /* 392 weights per output channel */

// ---------------------------------------------------------------------------
// Fully fused, register-resident sweep. One CTA per (b,c) 112x112 SPD matrix.
//   Phase 0: per-block sparse-tap compaction of conv weights (warp 0)
//   Phase 1: conv -> v1 tile into shared AO
//   Phase 2: each thread owns 25 lower-triangle elements IN REGISTERS.
//            112 symmetric sweep steps; per step only the pivot column goes
//            through shared (publish by owners -> cvec), update is
//            v -= (cvec[i]*rd)*cvec[j] in registers.
//            After all pivots: areg = -A^{-1}; pivot p value = L[p,p]^2.
//   Phase 3: out[i,j] = v1[i,j] * (Ainv[i,j]*rdiag[i] + 1)^2  (both mirrors)
// ---------------------------------------------------------------------------
extern __shared__ float smem[];

__global__ __launch_bounds__(T_, 3)
void fused_kernel(const float* __restrict__ x,
                  const float* __restrict__ w,
                  const float* __restrict__ bias,
                  float* __restrict__ out) {
    float* AO    = smem;             // N_*LD  (original v1, full square)
    float* cvec  = AO + N_ * LD;     // 128 (pivot column snapshot; pad zeroed)
    float* rdiag = cvec + 128;       // 128
    float* twv   = rdiag + 128;      // WPC tap weights
    int*   tkey  = (int*)(twv + WPC);
    __shared__ int s_ntap;

    const int m   = blockIdx.x;
    const int b   = m / C_;
    const int c   = m % C_;
    const int tid = threadIdx.x;

    // ---- Phase 0: compact nonzero taps of this output channel (warp 0) ----
    if (tid < 32) {
        int cnt = 0;
        for (int base = 0; base < WPC; base += 32) {
            const int idx = base + tid;
            const float val = (idx < WPC) ? __ldg(&w[c * WPC + idx]) : 0.0f;
            const unsigned msk = __ballot_sync(0xffffffffu, val != 0.0f);
            if (val != 0.0f) {
                const int pos = cnt + __popc(msk & ((1u << tid) - 1u));
                const int ci = idx / (KS * KS);
                const int r  = idx % (KS * KS);
                twv[pos]  = val;
                tkey[pos] = (ci << 16) | ((r / KS) << 8) | (r % KS);
            }
            cnt += __popc(msk);
        }
        if (tid == 0) s_ntap = cnt;
    }
    __syncthreads();

    // ---- Phase 1: conv -> AO ----
    {
        const float bc = __ldg(&bias[c]);
        const int nt = s_ntap;
        const float* __restrict__ xb = x + (size_t)b * C_ * NPIX;
        for (int p = tid; p < NPIX; p += T_) {
            const int i = p / N_;
            const int j = p - i * N_;
            float acc = bc;
            for (int t = 0; t < nt; ++t) {
                const int key = tkey[t];
                const int ci = key >> 16;
                const int ki = (key >> 8) & 255;
                const int kj = key & 255;
                const int ii = i + ki - HALO;
                const int jj = j + kj - HALO;
                if (ii >= 0 && ii < N_ && jj >= 0 && jj < N_)
                    acc += twv[t] * __ldg(&xb[(ci * N_ + ii) * N_ + jj]);
            }
            AO[i * LD + j] = acc;
        }
        // zero cvec padding so dummy elements (i=j=127) read 0.0
        if (tid < 16) cvec[112 + tid] = 0.0f;
    }
    __syncthreads();

    // ---- load my 25 elements into registers, precompute packed coords ----
    float areg[EPT];
    int   ij[EPT];
    int   ihi = 0;
    {
        const int f0 = tid * EPT;
        int i = (int)((sqrtf(8.0f * (float)f0 + 1.0f) - 1.0f) * 0.5f);
        while ((i + 1) * (i + 2) / 2 <= f0) ++i;
        while (i * (i + 1) / 2 > f0) --i;
        int j = f0 - i * (i + 1) / 2;
        #pragma unroll
        for (int k = 0; k < EPT; ++k) {
            const int f = f0 + k;
            if (f < NTRI) {
                ij[k]   = (i << 8) | j;
                areg[k] = AO[i * LD + j];
                ihi = i;
            } else {
                ij[k]   = (127 << 8) | 127;   // dummy: reads cvec[127]==0
                areg[k] = 0.0f;
            }
            if (++j > i) { j = 0; ++i; }
        }
    }

    // ---- Phase 2: symmetric sweep, 112 pivots, matrix in registers ----
    for (int p = 0; p < N_; ++p) {
        // publish pivot column (owners of row p / col p only)
        if (ihi >= p) {
            #pragma unroll
            for (int k = 0; k < EPT; ++k) {
                const int i = ij[k] >> 8;
                const int j = ij[k] & 255;
                if (i == p || j == p)
                    cvec[(i == p) ? j : i] = areg[k];
            }
        }
        __syncthreads();
        const float piv = cvec[p];
        const float rd  = 1.0f / piv;
        if (tid == 0) rdiag[p] = rsqrtf(piv);
        // rank-1 update in registers
        #pragma unroll
        for (int k = 0; k < EPT; ++k) {
            const int i = ij[k] >> 8;
            const int j = ij[k] & 255;
            const float ci = cvec[i];
            const float cj = cvec[j];
            const float cird = ci * rd;
            float v = fmaf(-cird, cj, areg[k]);
            if (i == p)      v = (j == p) ? -rd : cj * rd;
            else if (j == p) v = cird;
            areg[k] = v;
        }
        __syncthreads();
    }

    // ---- Phase 3: fused elementwise output (both mirrors per pair) ----
    {
        float* __restrict__ O = out + (size_t)m * NPIX;
        #pragma unroll
        for (int k = 0; k < EPT; ++k) {
            const int i = ij[k] >> 8;
            const int j = ij[k] & 255;
            if (i < N_) {
                const float ainv = -areg[k];         // A^{-1}[i][j], i>=j
                const float ri = rdiag[i];
                const float rj = rdiag[j];
                const float alo = AO[i * LD + j];
                const float ahi = AO[j * LD + i];
                const float u = fmaf(ainv, ri, 1.0f);
                const float v = fmaf(ainv, rj, 1.0f);
                O[i * N_ + j] = alo * u * u;
                O[j * N_ + i] = ahi * v * v;
            }
        }
    }
}

// ---------------------------------------------------------------------------
extern "C" void kernel_launch(void* const* d_in, const int* in_sizes, int n_in,
                              void* d_out, int out_size) {
    const float* x1   = (const float*)d_in[0];
    const float* w    = (const float*)d_in[1];
    const float* bias = (const float*)d_in[2];
    float* out = (float*)d_out;
    (void)in_sizes; (void)n_in; (void)out_size;

    static const int SMEM_BYTES =
        (int)((N_ * LD + 128 + 128 + WPC) * sizeof(float) + WPC * sizeof(int));

    cudaFuncSetAttribute(fused_kernel,
                         cudaFuncAttributeMaxDynamicSharedMemorySize,
                         SMEM_BYTES);

    fused_kernel<<<NMAT, T_, SMEM_BYTES>>>(x1, w, bias, out);
}

// round 7
// speedup vs baseline: 5.3576x; 5.3576x over previous
#include <cuda_runtime.h>
#include <math.h>

#define B_   64
#define C_   8
#define N_   112
#define LD   113
#define KS   7
#define HALO 3
#define NMAT (B_*C_)
#define NPIX (N_*N_)
#define T_   256
#define EPT  32                /* span width per thread */
#define WPC  (C_*KS*KS)        /* 392 weights per output channel */

// ---------------------------------------------------------------------------
// Register-resident symmetric sweep, structured spans. One CTA per matrix.
//   Each thread owns a 32-wide single-row span (i, j0..j0+31) of the lower
//   triangle (256 spans cover all 112 rows; j0-sorted for uniform warps).
//   Per pivot p: publish pivot column to cvec (row-p owners + one covering
//   thread per row), barrier, uniform in-register rank-1 update, barrier.
//   After all 112 pivots: areg = -A^{-1}; pivot value at step p = L[p,p]^2.
//   Output: out[i,j] = v1[i,j] * (Ainv[i,j]*rdiag[i] + 1)^2  (both mirrors)
// ---------------------------------------------------------------------------
extern __shared__ float smem[];

__global__ __launch_bounds__(T_, 3)
void fused_kernel(const float* __restrict__ x,
                  const float* __restrict__ w,
                  const float* __restrict__ bias,
                  float* __restrict__ out) {
    float* AO    = smem;             // N_*LD  (original v1, full square)
    float* cvec  = AO + N_ * LD;     // 128
    float* rdiag = cvec + 128;       // 128
    float* twv   = rdiag + 128;      // WPC tap weights
    int*   tkey  = (int*)(twv + WPC);
    __shared__ int s_ntap;

    const int m   = blockIdx.x;
    const int b   = m / C_;
    const int c   = m % C_;
    const int tid = threadIdx.x;

    // ---- Phase 0: compact nonzero taps of this output channel (warp 0) ----
    if (tid < 32) {
        int cnt = 0;
        for (int base = 0; base < WPC; base += 32) {
            const int idx = base + tid;
            const float val = (idx < WPC) ? __ldg(&w[c * WPC + idx]) : 0.0f;
            const unsigned msk = __ballot_sync(0xffffffffu, val != 0.0f);
            if (val != 0.0f) {
                const int pos = cnt + __popc(msk & ((1u << tid) - 1u));
                const int ci = idx / (KS * KS);
                const int r  = idx % (KS * KS);
                twv[pos]  = val;
                tkey[pos] = (ci << 16) | ((r / KS) << 8) | (r % KS);
            }
            cnt += __popc(msk);
        }
        if (tid == 0) s_ntap = cnt;
    }
    __syncthreads();

    // ---- Phase 1: conv -> AO ----
    {
        const float bc = __ldg(&bias[c]);
        const int nt = s_ntap;
        const float* __restrict__ xb = x + (size_t)b * C_ * NPIX;
        for (int p = tid; p < NPIX; p += T_) {
            const int i = p / N_;
            const int j = p - i * N_;
            float acc = bc;
            for (int t = 0; t < nt; ++t) {
                const int key = tkey[t];
                const int ci = key >> 16;
                const int ki = (key >> 8) & 255;
                const int kj = key & 255;
                const int ii = i + ki - HALO;
                const int jj = j + kj - HALO;
                if (ii >= 0 && ii < N_ && jj >= 0 && jj < N_)
                    acc += twv[t] * __ldg(&xb[(ci * N_ + ii) * N_ + jj]);
            }
            AO[i * LD + j] = acc;
        }
    }
    __syncthreads();

    // ---- span assignment (j0-sorted: warps have uniform j0) ----
    int i, j0;
    if (tid < 112)       { i = tid;        j0 = 0;  }
    else if (tid < 192)  { i = tid - 80;   j0 = 32; }
    else if (tid < 240)  { i = tid - 128;  j0 = 64; }
    else                 { i = tid - 144;  j0 = 96; }
    const int len = min(EPT, i + 1 - j0);

    // ---- load my span into registers ----
    float areg[EPT];
    #pragma unroll
    for (int k = 0; k < EPT; ++k)
        areg[k] = (k < len) ? AO[i * LD + j0 + k] : 0.0f;

    // ---- Phase 2: symmetric sweep, 112 pivots, matrix in registers ----
    for (int p = 0; p < N_; ++p) {
        // publish pivot column
        if (i == p) {
            #pragma unroll
            for (int k = 0; k < EPT; ++k)
                if (k < len) cvec[j0 + k] = areg[k];
        } else if (p <= i && p >= j0 && p < j0 + EPT) {
            const int kp = p - j0;
            #pragma unroll
            for (int k = 0; k < EPT; ++k)
                if (k == kp) cvec[i] = areg[k];
        }
        __syncthreads();
        const float piv = cvec[p];
        const float rd  = 1.0f / piv;
        if (tid == 0) rdiag[p] = rsqrtf(piv);
        if (i == p) {
            // my whole span is the pivot row
            #pragma unroll
            for (int k = 0; k < EPT; ++k) {
                const float cj = cvec[j0 + k];
                areg[k] = (j0 + k == p) ? -rd : cj * rd;
            }
        } else {
            const float ci   = cvec[i];
            const float cird = ci * rd;
            const int   kp   = p - j0;   // may be out of [0,EPT)
            #pragma unroll
            for (int k = 0; k < EPT; ++k) {
                const float cj = cvec[j0 + k];
                float v = fmaf(-cird, cj, areg[k]);
                if (k == kp) v = cird;   // element (i,p) fixup
                areg[k] = v;
            }
        }
        __syncthreads();
    }

    // ---- Phase 3: fused elementwise output (both mirrors per element) ----
    {
        float* __restrict__ O = out + (size_t)m * NPIX;
        #pragma unroll
        for (int k = 0; k < EPT; ++k) {
            if (k < len) {
                const int j = j0 + k;
                const float ainv = -areg[k];         // A^{-1}[i][j], i>=j
                const float ri = rdiag[i];
                const float rj = rdiag[j];
                const float alo = AO[i * LD + j];
                const float ahi = AO[j * LD + i];
                const float u = fmaf(ainv, ri, 1.0f);
                const float v = fmaf(ainv, rj, 1.0f);
                O[i * N_ + j] = alo * u * u;
                O[j * N_ + i] = ahi * v * v;
            }
        }
    }
}

// ---------------------------------------------------------------------------
extern "C" void kernel_launch(void* const* d_in, const int* in_sizes, int n_in,
                              void* d_out, int out_size) {
    const float* x1   = (const float*)d_in[0];
    const float* w    = (const float*)d_in[1];
    const float* bias = (const float*)d_in[2];
    float* out = (float*)d_out;
    (void)in_sizes; (void)n_in; (void)out_size;

    static const int SMEM_BYTES =
        (int)((N_ * LD + 128 + 128 + WPC) * sizeof(float) + WPC * sizeof(int));

    cudaFuncSetAttribute(fused_kernel,
                         cudaFuncAttributeMaxDynamicSharedMemorySize,
                         SMEM_BYTES);

    fused_kernel<<<NMAT, T_, SMEM_BYTES>>>(x1, w, bias, out);
}

// round 10
// speedup vs baseline: 6.0215x; 1.1239x over previous
#include <cuda_runtime.h>
#include <math.h>

#define B_   64
#define C_   8
#define N_   112
#define LD   113
#define KS   7
#define HALO 3
#define NMAT (B_*C_)
#define NPIX (N_*N_)
#define T_   256
#define EPT  32                /* span width per thread */
#define WPC  (C_*KS*KS)        /* 392 weights per output channel */

// ---------------------------------------------------------------------------
// Register-resident RANK-2 symmetric sweep. One CTA per 112x112 SPD matrix.
//   Each thread owns a 32-wide single-row span (i, j0..j0+31) of the lower
//   triangle. Per double-pivot (p,p+1): publish both pivot columns to shared
//   (c1,c2), barrier, block update  a -= u1*c1[j] + u2*c2[j]  with
//   (u1,u2) = (c1[i],c2[i])*D^{-1}, D = 2x2 pivot block. Pivot rows/cols get
//   D^{-1}-derived values. After all 112 pivots: areg = -A^{-1}.
//   rdiag[p] = rsqrt(d11), rdiag[p+1] = rsqrt(det/d11)  (= 1/L[p,p]).
//   Output: out[i,j] = v1[i,j] * (Ainv[i,j]*rdiag[i] + 1)^2  (both mirrors)
// ---------------------------------------------------------------------------
extern __shared__ float smem[];

__global__ __launch_bounds__(T_, 4)
void fused_kernel(const float* __restrict__ x,
                  const float* __restrict__ w,
                  const float* __restrict__ bias,
                  float* __restrict__ out) {
    float* AO    = smem;             // N_*LD  (original v1, full square)
    float* c1    = AO + N_ * LD;     // 128
    float* c2    = c1 + 128;         // 128
    float* rdiag = c2 + 128;         // 128
    float* twv   = rdiag + 128;      // WPC tap weights
    int*   tkey  = (int*)(twv + WPC);
    __shared__ int s_ntap;

    const int tid = threadIdx.x;

    // ---- Phase 0: compact nonzero taps of this output channel (warp 0) ----
    {
        const int c = blockIdx.x % C_;
        if (tid < 32) {
            int cnt = 0;
            for (int base = 0; base < WPC; base += 32) {
                const int idx = base + tid;
                const float val = (idx < WPC) ? __ldg(&w[c * WPC + idx]) : 0.0f;
                const unsigned msk = __ballot_sync(0xffffffffu, val != 0.0f);
                if (val != 0.0f) {
                    const int pos = cnt + __popc(msk & ((1u << tid) - 1u));
                    const int ci = idx / (KS * KS);
                    const int r  = idx % (KS * KS);
                    twv[pos]  = val;
                    tkey[pos] = (ci << 16) | ((r / KS) << 8) | (r % KS);
                }
                cnt += __popc(msk);
            }
            if (tid == 0) s_ntap = cnt;
        }
    }
    __syncthreads();

    // ---- Phase 1: conv -> AO ----
    {
        const int b = blockIdx.x / C_;
        const int c = blockIdx.x % C_;
        const float bc = __ldg(&bias[c]);
        const int nt = s_ntap;
        const float* __restrict__ xb = x + (size_t)b * C_ * NPIX;
        for (int p = tid; p < NPIX; p += T_) {
            const int pi = p / N_;
            const int pj = p - pi * N_;
            float acc = bc;
            for (int t = 0; t < nt; ++t) {
                const int key = tkey[t];
                const int ci = key >> 16;
                const int ki = (key >> 8) & 255;
                const int kj = key & 255;
                const int ii = pi + ki - HALO;
                const int jj = pj + kj - HALO;
                if (ii >= 0 && ii < N_ && jj >= 0 && jj < N_)
                    acc += twv[t] * __ldg(&xb[(ci * N_ + ii) * N_ + jj]);
            }
            AO[pi * LD + pj] = acc;
        }
    }
    __syncthreads();

    // ---- span assignment (j0-sorted: warps have uniform j0) ----
    int i, j0;
    if (tid < 112)       { i = tid;        j0 = 0;  }
    else if (tid < 192)  { i = tid - 80;   j0 = 32; }
    else if (tid < 240)  { i = tid - 128;  j0 = 64; }
    else                 { i = tid - 144;  j0 = 96; }
    const int len = min(EPT, i + 1 - j0);

    // ---- load my span into registers ----
    float areg[EPT];
    #pragma unroll
    for (int k = 0; k < EPT; ++k)
        areg[k] = (k < len) ? AO[i * LD + j0 + k] : 0.0f;

    // ---- Phase 2: rank-2 symmetric sweep, 56 double-pivots ----
    for (int p = 0; p < N_; p += 2) {
        const int kp = p - j0;          // may be out of [0,EPT)
        // publish pivot columns p (c1) and p+1 (c2), pre-step values
        if (i == p) {
            #pragma unroll
            for (int k = 0; k < EPT; ++k)
                if (k < len) c1[j0 + k] = areg[k];
        } else if (i == p + 1) {
            #pragma unroll
            for (int k = 0; k < EPT; ++k)
                if (k < len) c2[j0 + k] = areg[k];
        } else if (i > p + 1 && kp >= -1 && kp < EPT) {
            #pragma unroll
            for (int k = 0; k < EPT; ++k) {
                if (k == kp)     c1[i] = areg[k];
                if (k == kp + 1) c2[i] = areg[k];
            }
        }
        __syncthreads();
        const float d11 = c1[p];
        const float d12 = c2[p];
        const float d22 = c2[p + 1];
        const float det = d11 * d22 - d12 * d12;
        const float rdet = 1.0f / det;
        if (tid == p) {                  // thread (i=p, j0=0) always exists
            rdiag[p]     = rsqrtf(d11);
            rdiag[p + 1] = rsqrtf(det / d11);
        }
        if (i == p) {
            #pragma unroll
            for (int k = 0; k < EPT; ++k) {
                const float nv = (d22 * areg[k] - d12 * c2[j0 + k]) * rdet;
                areg[k] = (k == kp) ? (-d22 * rdet) : nv;
            }
        } else if (i == p + 1) {
            #pragma unroll
            for (int k = 0; k < EPT; ++k) {
                const float nv = (d11 * areg[k] - d12 * c1[j0 + k]) * rdet;
                areg[k] = (k == kp) ? (d12 * rdet)
                        : ((k == kp + 1) ? (-d11 * rdet) : nv);
            }
        } else {
            const float ci1 = c1[i];
            const float ci2 = c2[i];
            const float u1 = (ci1 * d22 - ci2 * d12) * rdet;
            const float u2 = (ci2 * d11 - ci1 * d12) * rdet;
            #pragma unroll
            for (int k = 0; k < EPT; ++k)
                areg[k] = fmaf(-u1, c1[j0 + k],
                          fmaf(-u2, c2[j0 + k], areg[k]));
            if (i > p + 1 && kp >= -1 && kp < EPT) {
                #pragma unroll
                for (int k = 0; k < EPT; ++k) {
                    if (k == kp)     areg[k] = u1;
                    if (k == kp + 1) areg[k] = u2;
                }
            }
        }
        __syncthreads();
    }

    // ---- Phase 3: fused elementwise output (both mirrors per element) ----
    {
        float* __restrict__ O = out + (size_t)blockIdx.x * NPIX;
        #pragma unroll
        for (int k = 0; k < EPT; ++k) {
            if (k < len) {
                const int j = j0 + k;
                const float ainv = -areg[k];         // A^{-1}[i][j], i>=j
                const float ri = rdiag[i];
                const float rj = rdiag[j];
                const float alo = AO[i * LD + j];
                const float ahi = AO[j * LD + i];
                const float u = fmaf(ainv, ri, 1.0f);
                const float v = fmaf(ainv, rj, 1.0f);
                O[i * N_ + j] = alo * u * u;
                O[j * N_ + i] = ahi * v * v;
            }
        }
    }
}

// ---------------------------------------------------------------------------
extern "C" void kernel_launch(void* const* d_in, const int* in_sizes, int n_in,
                              void* d_out, int out_size) {
    const float* x1   = (const float*)d_in[0];
    const float* w    = (const float*)d_in[1];
    const float* bias = (const float*)d_in[2];
    float* out = (float*)d_out;
    (void)in_sizes; (void)n_in; (void)out_size;

    static const int SMEM_BYTES =
        (int)((N_ * LD + 3 * 128 + WPC) * sizeof(float) + WPC * sizeof(int));

    cudaFuncSetAttribute(fused_kernel,
                         cudaFuncAttributeMaxDynamicSharedMemorySize,
                         SMEM_BYTES);

    fused_kernel<<<NMAT, T_, SMEM_BYTES>>>(x1, w, bias, out);
}

// round 11
// speedup vs baseline: 6.3395x; 1.0528x over previous
#include <cuda_runtime.h>
#include <math.h>

#define B_   64
#define C_   8
#define N_   112
#define LD   113
#define KS   7
#define HALO 3
#define NMAT (B_*C_)
#define NPIX (N_*N_)
#define T_   256
#define EPT  32                /* span width per thread */
#define WPC  (C_*KS*KS)        /* 392 weights per output channel */

// ---------------------------------------------------------------------------
// Register-resident RANK-2 symmetric sweep, float2-packed pivot columns.
// One CTA per 112x112 SPD matrix. Each thread owns a 32-wide single-row span
// (i, j0..j0+31) of the lower triangle.
// Per double-pivot (p,p+1): publish both pivot columns into c12[] (.x = col p,
// .y = col p+1), barrier, block update  a -= u1*c.x + u2*c.y  with
// (u1,u2) = (c12[i].x, c12[i].y) * D^{-1}, D = 2x2 pivot block.
// Hot loop: 1 LDS.64 + 2 FMA per element per 2 pivots.
// After all pivots: areg = -A^{-1}; rdiag[p]=rsqrt(d11), rdiag[p+1]=
// rsqrt(det/d11) (= 1/L[p,p]).  Output:
//   out[i,j] = v1[i,j] * (Ainv[i,j]*rdiag[i] + 1)^2   (both mirrors)
// ---------------------------------------------------------------------------
extern __shared__ float smem[];

__global__ __launch_bounds__(T_, 4)
void fused_kernel(const float* __restrict__ x,
                  const float* __restrict__ w,
                  const float* __restrict__ bias,
                  float* __restrict__ out) {
    float2* c12  = (float2*)smem;            // 128 float2 (1024 B, aligned)
    float* rdiag = smem + 256;               // 128
    float* AO    = rdiag + 128;              // N_*LD  (original v1, full)
    float* twv   = AO + N_ * LD;             // WPC tap weights
    int*   tkey  = (int*)(twv + WPC);
    __shared__ int s_ntap;

    const int tid = threadIdx.x;

    // ---- Phase 0: compact nonzero taps of this output channel (warp 0) ----
    {
        const int c = blockIdx.x % C_;
        if (tid < 32) {
            int cnt = 0;
            for (int base = 0; base < WPC; base += 32) {
                const int idx = base + tid;
                const float val = (idx < WPC) ? __ldg(&w[c * WPC + idx]) : 0.0f;
                const unsigned msk = __ballot_sync(0xffffffffu, val != 0.0f);
                if (val != 0.0f) {
                    const int pos = cnt + __popc(msk & ((1u << tid) - 1u));
                    const int ci = idx / (KS * KS);
                    const int r  = idx % (KS * KS);
                    twv[pos]  = val;
                    tkey[pos] = (ci << 16) | ((r / KS) << 8) | (r % KS);
                }
                cnt += __popc(msk);
            }
            if (tid == 0) s_ntap = cnt;
        }
    }
    __syncthreads();

    // ---- Phase 1: conv -> AO ----
    {
        const int b = blockIdx.x / C_;
        const int c = blockIdx.x % C_;
        const float bc = __ldg(&bias[c]);
        const int nt = s_ntap;
        const float* __restrict__ xb = x + (size_t)b * C_ * NPIX;
        for (int p = tid; p < NPIX; p += T_) {
            const int pi = p / N_;
            const int pj = p - pi * N_;
            float acc = bc;
            for (int t = 0; t < nt; ++t) {
                const int key = tkey[t];
                const int ci = key >> 16;
                const int ki = (key >> 8) & 255;
                const int kj = key & 255;
                const int ii = pi + ki - HALO;
                const int jj = pj + kj - HALO;
                if (ii >= 0 && ii < N_ && jj >= 0 && jj < N_)
                    acc += twv[t] * __ldg(&xb[(ci * N_ + ii) * N_ + jj]);
            }
            AO[pi * LD + pj] = acc;
        }
    }
    __syncthreads();

    // ---- span assignment (j0-sorted: warps have uniform j0) ----
    int i, j0;
    if (tid < 112)       { i = tid;        j0 = 0;  }
    else if (tid < 192)  { i = tid - 80;   j0 = 32; }
    else if (tid < 240)  { i = tid - 128;  j0 = 64; }
    else                 { i = tid - 144;  j0 = 96; }

    // ---- load my span into registers ----
    float areg[EPT];
    {
        const int len = min(EPT, i + 1 - j0);
        #pragma unroll
        for (int k = 0; k < EPT; ++k)
            areg[k] = (k < len) ? AO[i * LD + j0 + k] : 0.0f;
    }

    // ---- Phase 2: rank-2 symmetric sweep, 56 double-pivots ----
    for (int p = 0; p < N_; p += 2) {
        const int kp = p - j0;          // may be out of [0,EPT)
        // publish pivot columns p (.x) and p+1 (.y), pre-step values
        if (i == p) {
            const int len = i + 1 - j0;  // <= EPT on pivot rows' spans
            #pragma unroll
            for (int k = 0; k < EPT; ++k)
                if (k < len) c12[j0 + k].x = areg[k];
        } else if (i == p + 1) {
            const int len = min(EPT, i + 1 - j0);
            #pragma unroll
            for (int k = 0; k < EPT; ++k)
                if (k < len) c12[j0 + k].y = areg[k];
        } else if (i > p + 1 && kp >= -1 && kp < EPT) {
            #pragma unroll
            for (int k = 0; k < EPT; ++k) {
                if (k == kp)     c12[i].x = areg[k];
                if (k == kp + 1) c12[i].y = areg[k];
            }
        }
        __syncthreads();
        const float2 dp  = c12[p];
        const float  d11 = dp.x;
        const float  d12 = dp.y;
        const float  d22 = c12[p + 1].y;
        const float  rdet = 1.0f / (d11 * d22 - d12 * d12);
        if (tid == p) {                  // thread (i=p, j0=0) always exists
            rdiag[p]     = rsqrtf(d11);
            rdiag[p + 1] = rsqrtf((d11 * d22 - d12 * d12) / d11);
        }
        if (i == p) {
            #pragma unroll
            for (int k = 0; k < EPT; ++k) {
                const float nv = (d22 * areg[k] - d12 * c12[j0 + k].y) * rdet;
                areg[k] = (k == kp) ? (-d22 * rdet) : nv;
            }
        } else if (i == p + 1) {
            #pragma unroll
            for (int k = 0; k < EPT; ++k) {
                const float nv = (d11 * areg[k] - d12 * c12[j0 + k].x) * rdet;
                areg[k] = (k == kp) ? (d12 * rdet)
                        : ((k == kp + 1) ? (-d11 * rdet) : nv);
            }
        } else {
            const float2 ciw = c12[i];
            const float u1 = (ciw.x * d22 - ciw.y * d12) * rdet;
            const float u2 = (ciw.y * d11 - ciw.x * d12) * rdet;
            #pragma unroll
            for (int k = 0; k < EPT; ++k) {
                const float2 cc = c12[j0 + k];
                areg[k] = fmaf(-u1, cc.x, fmaf(-u2, cc.y, areg[k]));
            }
            if (i > p + 1 && kp >= -1 && kp < EPT) {
                #pragma unroll
                for (int k = 0; k < EPT; ++k) {
                    if (k == kp)     areg[k] = u1;
                    if (k == kp + 1) areg[k] = u2;
                }
            }
        }
        __syncthreads();
    }

    // ---- Phase 3: fused elementwise output (both mirrors per element) ----
    {
        float* __restrict__ O = out + (size_t)blockIdx.x * NPIX;
        const int len = min(EPT, i + 1 - j0);
        const float ri = rdiag[i];
        #pragma unroll
        for (int k = 0; k < EPT; ++k) {
            if (k < len) {
                const int j = j0 + k;
                const float ainv = -areg[k];         // A^{-1}[i][j], i>=j
                const float rj = rdiag[j];
                const float alo = AO[i * LD + j];
                const float ahi = AO[j * LD + i];
                const float u = fmaf(ainv, ri, 1.0f);
                const float v = fmaf(ainv, rj, 1.0f);
                O[i * N_ + j] = alo * u * u;
                O[j * N_ + i] = ahi * v * v;
            }
        }
    }
}

// ---------------------------------------------------------------------------
extern "C" void kernel_launch(void* const* d_in, const int* in_sizes, int n_in,
                              void* d_out, int out_size) {
    const float* x1   = (const float*)d_in[0];
    const float* w    = (const float*)d_in[1];
    const float* bias = (const float*)d_in[2];
    float* out = (float*)d_out;
    (void)in_sizes; (void)n_in; (void)out_size;

    static const int SMEM_BYTES =
        (int)((256 + 128 + N_ * LD + WPC) * sizeof(float) + WPC * sizeof(int));

    cudaFuncSetAttribute(fused_kernel,
                         cudaFuncAttributeMaxDynamicSharedMemorySize,
                         SMEM_BYTES);

    fused_kernel<<<NMAT, T_, SMEM_BYTES>>>(x1, w, bias, out);
}

// round 13
// speedup vs baseline: 8.6443x; 1.3635x over previous
#include <cuda_runtime.h>
#include <math.h>

#define B_   64
#define C_   8
#define N_   112
#define LD   113
#define KS   7
#define HALO 3
#define NMAT (B_*C_)
#define NPIX (N_*N_)
#define T_   256
#define EPT  32                /* span width per thread */
#define WPC  (C_*KS*KS)        /* 392 weights per output channel */

typedef unsigned long long ull;

// packed f32x2 helpers (Blackwell packed fp32 math; PTX-only)
__device__ __forceinline__ ull pk2(float x, float y) {
    ull v; asm("mov.b64 %0, {%1,%2};" : "=l"(v) : "f"(x), "f"(y)); return v;
}
__device__ __forceinline__ float lo32(ull v) {
    float x, y; asm("mov.b64 {%0,%1}, %2;" : "=f"(x), "=f"(y) : "l"(v)); return x;
}
__device__ __forceinline__ float hi32(ull v) {
    float x, y; asm("mov.b64 {%0,%1}, %2;" : "=f"(x), "=f"(y) : "l"(v)); return y;
}
#define FFMA2(a, m, s) \
    asm("fma.rn.f32x2 %0, %1, %2, %3;" : "=l"(a) : "l"(m), "l"(s), "l"(a))

// ---------------------------------------------------------------------------
// Register-resident RANK-2 symmetric sweep, f32x2-packed accumulators.
// One CTA per 112x112 SPD matrix; thread owns a 32-wide single-row span
// (i, j0..j0+31) of the lower triangle, held packed in areg2[16] (ull).
// Per double-pivot (p,p+1): publish columns p,p+1 into c1v/c2v, barrier,
// update  a -= u1*c1[j] + u2*c2[j]  via LDS.128 + fma.rn.f32x2
// (6 instructions per 4 elements). D = 2x2 pivot block, (u1,u2)=(c1[i],c2[i])D^{-1}.
// After all pivots: areg = -A^{-1}; rdiag[p]=rsqrt(d11), rdiag[p+1]=rsqrt(det/d11).
// Output: out[i,j] = v1[i,j] * (Ainv[i,j]*rdiag[i] + 1)^2  (both mirrors)
// ---------------------------------------------------------------------------
extern __shared__ float smem[];

__global__ __launch_bounds__(T_, 4)
void fused_kernel(const float* __restrict__ x,
                  const float* __restrict__ w,
                  const float* __restrict__ bias,
                  float* __restrict__ out) {
    float* c1v   = smem;                 // 128 (16B aligned)
    float* c2v   = c1v + 128;            // 128
    float* rdiag = c2v + 128;            // 128
    float* AO    = rdiag + 128;          // N_*LD  (original v1, full)
    float* twv   = AO + N_ * LD;         // WPC tap weights
    int*   tkey  = (int*)(twv + WPC);
    __shared__ int s_ntap;

    const int tid = threadIdx.x;

    // ---- Phase 0: compact nonzero taps of this output channel (warp 0) ----
    {
        const int c = blockIdx.x % C_;
        if (tid < 32) {
            int cnt = 0;
            for (int base = 0; base < WPC; base += 32) {
                const int idx = base + tid;
                const float val = (idx < WPC) ? __ldg(&w[c * WPC + idx]) : 0.0f;
                const unsigned msk = __ballot_sync(0xffffffffu, val != 0.0f);
                if (val != 0.0f) {
                    const int pos = cnt + __popc(msk & ((1u << tid) - 1u));
                    const int ci = idx / (KS * KS);
                    const int r  = idx % (KS * KS);
                    twv[pos]  = val;
                    tkey[pos] = (ci << 16) | ((r / KS) << 8) | (r % KS);
                }
                cnt += __popc(msk);
            }
            if (tid == 0) s_ntap = cnt;
        }
    }
    __syncthreads();

    // ---- Phase 1: conv -> AO ----
    {
        const int b = blockIdx.x / C_;
        const int c = blockIdx.x % C_;
        const float bc = __ldg(&bias[c]);
        const int nt = s_ntap;
        const float* __restrict__ xb = x + (size_t)b * C_ * NPIX;
        for (int p = tid; p < NPIX; p += T_) {
            const int pi = p / N_;
            const int pj = p - pi * N_;
            float acc = bc;
            for (int t = 0; t < nt; ++t) {
                const int key = tkey[t];
                const int ci = key >> 16;
                const int ki = (key >> 8) & 255;
                const int kj = key & 255;
                const int ii = pi + ki - HALO;
                const int jj = pj + kj - HALO;
                if (ii >= 0 && ii < N_ && jj >= 0 && jj < N_)
                    acc += twv[t] * __ldg(&xb[(ci * N_ + ii) * N_ + jj]);
            }
            AO[pi * LD + pj] = acc;
        }
    }
    __syncthreads();

    // ---- span assignment (j0-sorted: warps have uniform j0) ----
    int i, j0;
    if (tid < 112)       { i = tid;        j0 = 0;  }
    else if (tid < 192)  { i = tid - 80;   j0 = 32; }
    else if (tid < 240)  { i = tid - 128;  j0 = 64; }
    else                 { i = tid - 144;  j0 = 96; }

    // ---- load my span into packed registers ----
    ull areg2[EPT / 2];
    {
        const int len = min(EPT, i + 1 - j0);
        #pragma unroll
        for (int k = 0; k < EPT; k += 2) {
            const float a0 = (k < len)     ? AO[i * LD + j0 + k]     : 0.0f;
            const float a1 = (k + 1 < len) ? AO[i * LD + j0 + k + 1] : 0.0f;
            areg2[k >> 1] = pk2(a0, a1);
        }
    }

    // ---- Phase 2: rank-2 symmetric sweep, 56 double-pivots ----
    for (int p = 0; p < N_; p += 2) {
        const int kp = p - j0;          // may be out of [0,EPT)
        const int kq = kp >> 1;
        const bool odd = (kp & 1) != 0;
        // publish pivot columns p (c1v) and p+1 (c2v), pre-step values
        if (i == p) {
            const int len = min(EPT, i + 1 - j0);
            #pragma unroll
            for (int k = 0; k < EPT; k += 2) {
                const ull v = areg2[k >> 1];
                if (k < len)     c1v[j0 + k]     = lo32(v);
                if (k + 1 < len) c1v[j0 + k + 1] = hi32(v);
            }
        } else if (i == p + 1) {
            const int len = min(EPT, i + 1 - j0);
            #pragma unroll
            for (int k = 0; k < EPT; k += 2) {
                const ull v = areg2[k >> 1];
                if (k < len)     c2v[j0 + k]     = lo32(v);
                if (k + 1 < len) c2v[j0 + k + 1] = hi32(v);
            }
        } else if (i > p + 1 && kp >= -1 && kp < EPT) {
            if (!odd) {                 // kp even: both lanes in pair kq
                #pragma unroll
                for (int q = 0; q < EPT / 2; ++q)
                    if (q == kq) {
                        const ull v = areg2[q];
                        c1v[i] = lo32(v);
                        c2v[i] = hi32(v);
                    }
            } else {                    // kp odd: hi of kq, lo of kq+1
                #pragma unroll
                for (int q = 0; q < EPT / 2; ++q) {
                    if (q == kq && kp >= 0)           c1v[i] = hi32(areg2[q]);
                    if (q == kq + 1 && kp + 1 < EPT)  c2v[i] = lo32(areg2[q]);
                }
            }
        }
        __syncthreads();
        const float d11 = c1v[p];
        const float d12 = c2v[p];
        const float d22 = c2v[p + 1];
        const float det = d11 * d22 - d12 * d12;
        const float rdet = 1.0f / det;
        if (tid == p) {                  // thread (i=p, j0=0) always exists
            rdiag[p]     = rsqrtf(d11);
            rdiag[p + 1] = rsqrtf(det / d11);
        }
        if (i == p) {
            #pragma unroll
            for (int k = 0; k < EPT; k += 2) {
                const ull v = areg2[k >> 1];
                float n0 = (d22 * lo32(v) - d12 * c2v[j0 + k])     * rdet;
                float n1 = (d22 * hi32(v) - d12 * c2v[j0 + k + 1]) * rdet;
                if (k == kp)     n0 = -d22 * rdet;
                if (k + 1 == kp) n1 = -d22 * rdet;
                areg2[k >> 1] = pk2(n0, n1);
            }
        } else if (i == p + 1) {
            #pragma unroll
            for (int k = 0; k < EPT; k += 2) {
                const ull v = areg2[k >> 1];
                float n0 = (d11 * lo32(v) - d12 * c1v[j0 + k])     * rdet;
                float n1 = (d11 * hi32(v) - d12 * c1v[j0 + k + 1]) * rdet;
                if (k == kp)         n0 = d12 * rdet;     // col p
                if (k + 1 == kp)     n1 = d12 * rdet;     // col p
                if (k == kp + 1)     n0 = -d11 * rdet;    // col p+1 (diag)
                if (k + 1 == kp + 1) n1 = -d11 * rdet;    // col p+1 (diag)
                areg2[k >> 1] = pk2(n0, n1);
            }
        } else {
            const float c1i = c1v[i];
            const float c2i = c2v[i];
            const float u1 = (c1i * d22 - c2i * d12) * rdet;
            const float u2 = (c2i * d11 - c1i * d12) * rdet;
            const ull nu1 = pk2(-u1, -u1);
            const ull nu2 = pk2(-u2, -u2);
            const ulonglong2* __restrict__ C1 = (const ulonglong2*)(c1v + j0);
            const ulonglong2* __restrict__ C2 = (const ulonglong2*)(c2v + j0);
            #pragma unroll
            for (int k = 0; k < EPT; k += 4) {
                const ulonglong2 w1 = C1[k >> 2];
                const ulonglong2 w2 = C2[k >> 2];
                FFMA2(areg2[k >> 1],       nu2, w2.x);
                FFMA2(areg2[k >> 1],       nu1, w1.x);
                FFMA2(areg2[(k >> 1) + 1], nu2, w2.y);
                FFMA2(areg2[(k >> 1) + 1], nu1, w1.y);
            }
            if (i > p + 1 && kp >= -1 && kp < EPT) {
                if (!odd) {             // kp even: whole pair kq = (u1,u2)
                    const ull pu = pk2(u1, u2);
                    #pragma unroll
                    for (int q = 0; q < EPT / 2; ++q)
                        if (q == kq) areg2[q] = pu;
                } else {                // kp odd: hi of kq = u1, lo of kq+1 = u2
                    #pragma unroll
                    for (int q = 0; q < EPT / 2; ++q) {
                        if (q == kq && kp >= 0)
                            areg2[q] = pk2(lo32(areg2[q]), u1);
                        if (q == kq + 1 && kp + 1 < EPT)
                            areg2[q] = pk2(u2, hi32(areg2[q]));
                    }
                }
            }
        }
        __syncthreads();
    }

    // ---- Phase 3: fused elementwise output (both mirrors per element) ----
    {
        float* __restrict__ O = out + (size_t)blockIdx.x * NPIX;
        const int len = min(EPT, i + 1 - j0);
        const float ri = rdiag[i];
        #pragma unroll
        for (int k = 0; k < EPT; ++k) {
            if (k < len) {
                const int j = j0 + k;
                const ull pv = areg2[k >> 1];
                const float ainv = -((k & 1) ? hi32(pv) : lo32(pv));
                const float rj = rdiag[j];
                const float alo = AO[i * LD + j];
                const float ahi = AO[j * LD + i];
                const float u = fmaf(ainv, ri, 1.0f);
                const float v = fmaf(ainv, rj, 1.0f);
                O[i * N_ + j] = alo * u * u;
                O[j * N_ + i] = ahi * v * v;
            }
        }
    }
}

// ---------------------------------------------------------------------------
extern "C" void kernel_launch(void* const* d_in, const int* in_sizes, int n_in,
                              void* d_out, int out_size) {
    const float* x1   = (const float*)d_in[0];
    const float* w    = (const float*)d_in[1];
    const float* bias = (const float*)d_in[2];
    float* out = (float*)d_out;
    (void)in_sizes; (void)n_in; (void)out_size;

    static const int SMEM_BYTES =
        (int)((384 + N_ * LD + WPC) * sizeof(float) + WPC * sizeof(int));

    cudaFuncSetAttribute(fused_kernel,
                         cudaFuncAttributeMaxDynamicSharedMemorySize,
                         SMEM_BYTES);

    fused_kernel<<<NMAT, T_, SMEM_BYTES>>>(x1, w, bias, out);
}